// round 13
// baseline (speedup 1.0000x reference)
#include <cuda_runtime.h>

// PerfectSpatialHash: out[i] = hash_table[(trunc(c*m0)+offset_table[trunc(c*m1)%64])%256]
// HASH=256, OFFSET=64, FEAT=8, N=4,000,000
//
// Strategy: 4 queries per thread.
//  - coords: 3x int4 coalesced loads (48B per thread, 16B-aligned)
//  - offset_table (3MB): L2-resident gathers via __ldg
//  - hash_table (512MB): random 32B-aligned gathers via 2x __ldcs float4 (evict-first)
//  - out: 2x __stcs float4 per query (streaming store, no L2 pollution)
//  - all table indices kept in 32-bit (max 2^25) to shorten the index ALU chain

__global__ __launch_bounds__(256)
void psh_kernel(const int* __restrict__ coords,
                const float4* __restrict__ hash_table,
                const int* __restrict__ offset_table,
                const float* __restrict__ m0,
                const float* __restrict__ m1,
                float4* __restrict__ out,
                int nq)
{
    const int t = blockIdx.x * blockDim.x + threadIdx.x;
    const int q0 = t * 4;
    if (q0 >= nq) return;

    const float m0x = __ldg(m0 + 0), m0y = __ldg(m0 + 1), m0z = __ldg(m0 + 2);
    const float m1x = __ldg(m1 + 0), m1y = __ldg(m1 + 1), m1z = __ldg(m1 + 2);

    int cs[12];
    if (q0 + 3 < nq) {
        // 48*t bytes is 16B-aligned -> 3 vector loads
        const int4* cp = reinterpret_cast<const int4*>(coords) + 3 * t;
        int4 a = __ldg(cp + 0);
        int4 b = __ldg(cp + 1);
        int4 c = __ldg(cp + 2);
        cs[0] = a.x; cs[1] = a.y; cs[2]  = a.z; cs[3]  = a.w;
        cs[4] = b.x; cs[5] = b.y; cs[6]  = b.z; cs[7]  = b.w;
        cs[8] = c.x; cs[9] = c.y; cs[10] = c.z; cs[11] = c.w;
    } else {
        #pragma unroll
        for (int q = 0; q < 4; q++) {
            if (q0 + q < nq) {
                cs[3*q + 0] = coords[(q0 + q) * 3 + 0];
                cs[3*q + 1] = coords[(q0 + q) * 3 + 1];
                cs[3*q + 2] = coords[(q0 + q) * 3 + 2];
            } else {
                cs[3*q + 0] = 0; cs[3*q + 1] = 0; cs[3*q + 2] = 0;
            }
        }
    }

    // Stage 1: offset-table indices (floored mod 64 == &63, valid for negatives too)
    int obase[4];
    #pragma unroll
    for (int q = 0; q < 4; q++) {
        int ox = ((int)((float)cs[3*q + 0] * m1x)) & 63;
        int oy = ((int)((float)cs[3*q + 1] * m1y)) & 63;
        int oz = ((int)((float)cs[3*q + 2] * m1z)) & 63;
        obase[q] = ((ox * 64 + oy) * 64 + oz) * 3;
    }

    // Stage 2: gather offsets (L2-resident, 3MB table) — all 12 loads in flight
    int offx[4], offy[4], offz[4];
    #pragma unroll
    for (int q = 0; q < 4; q++) {
        offx[q] = __ldg(offset_table + obase[q] + 0);
        offy[q] = __ldg(offset_table + obase[q] + 1);
        offz[q] = __ldg(offset_table + obase[q] + 2);
    }

    // Stage 3: hash indices (floored mod 256 == &255); max index 2^25 fits in int32
    int hbase[4];
    #pragma unroll
    for (int q = 0; q < 4; q++) {
        int hx = (((int)((float)cs[3*q + 0] * m0x)) + offx[q]) & 255;
        int hy = (((int)((float)cs[3*q + 1] * m0y)) + offy[q]) & 255;
        int hz = (((int)((float)cs[3*q + 2] * m0z)) + offz[q]) & 255;
        // float4 index: each entry is 8 floats = 2 float4
        hbase[q] = ((hx * 256 + hy) * 256 + hz) * 2;
    }

    // Stage 4: gather 32B features per query (random DRAM, streaming hint)
    float4 f0[4], f1[4];
    #pragma unroll
    for (int q = 0; q < 4; q++) {
        f0[q] = __ldcs(hash_table + hbase[q] + 0);
        f1[q] = __ldcs(hash_table + hbase[q] + 1);
    }

    // Stage 5: streaming stores (no reuse -> evict-first)
    #pragma unroll
    for (int q = 0; q < 4; q++) {
        if (q0 + q < nq) {
            __stcs(out + (q0 + q) * 2 + 0, f0[q]);
            __stcs(out + (q0 + q) * 2 + 1, f1[q]);
        }
    }
}

extern "C" void kernel_launch(void* const* d_in, const int* in_sizes, int n_in,
                              void* d_out, int out_size)
{
    const int*    coords     = (const int*)   d_in[0];
    const float4* hash_table = (const float4*)d_in[1];
    const int*    offset_tab = (const int*)   d_in[2];
    const float*  m0         = (const float*) d_in[3];
    const float*  m1         = (const float*) d_in[4];
    float4*       out        = (float4*)      d_out;

    const int nq = in_sizes[0] / 3;
    const int nthreads = (nq + 3) / 4;
    const int block = 256;
    const int grid = (nthreads + block - 1) / block;
    psh_kernel<<<grid, block>>>(coords, hash_table, offset_tab, m0, m1, out, nq);
}

// round 15
// speedup vs baseline: 1.0362x; 1.0362x over previous
#include <cuda_runtime.h>

// PerfectSpatialHash: out[i] = hash_table[(trunc(c*m0)+offset_table[trunc(c*m1)%64])%256]
// HASH=256, OFFSET=64, FEAT=8, N=4,000,000
//
// R13: measured 121us @ DRAM 64.3%, 608MB traffic (2x ideal). Evict-first hint on
// hash gathers was destroying L2 line-reuse (~38% of queries re-touch a 128B line)
// and offset-table retention. This round: default cache policy on hash gathers.
//
// Strategy: 4 queries per thread.
//  - coords: 3x int4 coalesced loads (48B per thread, 16B-aligned)
//  - offset_table (3MB): gathers via __ldg (want L2-resident)
//  - hash_table (512MB): random 32B-aligned gathers, DEFAULT policy (allow L2 reuse)
//  - out: 2x __stcs float4 per query (evict-first store, reduce L2 churn)
//  - all table indices kept in 32-bit (max 2^25) to shorten the index ALU chain

__global__ __launch_bounds__(256)
void psh_kernel(const int* __restrict__ coords,
                const float4* __restrict__ hash_table,
                const int* __restrict__ offset_table,
                const float* __restrict__ m0,
                const float* __restrict__ m1,
                float4* __restrict__ out,
                int nq)
{
    const int t = blockIdx.x * blockDim.x + threadIdx.x;
    const int q0 = t * 4;
    if (q0 >= nq) return;

    const float m0x = __ldg(m0 + 0), m0y = __ldg(m0 + 1), m0z = __ldg(m0 + 2);
    const float m1x = __ldg(m1 + 0), m1y = __ldg(m1 + 1), m1z = __ldg(m1 + 2);

    int cs[12];
    if (q0 + 3 < nq) {
        // 48*t bytes is 16B-aligned -> 3 vector loads
        const int4* cp = reinterpret_cast<const int4*>(coords) + 3 * t;
        int4 a = __ldg(cp + 0);
        int4 b = __ldg(cp + 1);
        int4 c = __ldg(cp + 2);
        cs[0] = a.x; cs[1] = a.y; cs[2]  = a.z; cs[3]  = a.w;
        cs[4] = b.x; cs[5] = b.y; cs[6]  = b.z; cs[7]  = b.w;
        cs[8] = c.x; cs[9] = c.y; cs[10] = c.z; cs[11] = c.w;
    } else {
        #pragma unroll
        for (int q = 0; q < 4; q++) {
            if (q0 + q < nq) {
                cs[3*q + 0] = coords[(q0 + q) * 3 + 0];
                cs[3*q + 1] = coords[(q0 + q) * 3 + 1];
                cs[3*q + 2] = coords[(q0 + q) * 3 + 2];
            } else {
                cs[3*q + 0] = 0; cs[3*q + 1] = 0; cs[3*q + 2] = 0;
            }
        }
    }

    // Stage 1: offset-table indices (floored mod 64 == &63, valid for negatives too)
    int obase[4];
    #pragma unroll
    for (int q = 0; q < 4; q++) {
        int ox = ((int)((float)cs[3*q + 0] * m1x)) & 63;
        int oy = ((int)((float)cs[3*q + 1] * m1y)) & 63;
        int oz = ((int)((float)cs[3*q + 2] * m1z)) & 63;
        obase[q] = ((ox * 64 + oy) * 64 + oz) * 3;
    }

    // Stage 2: gather offsets (3MB table, want L2-resident) — all 12 loads in flight
    int offx[4], offy[4], offz[4];
    #pragma unroll
    for (int q = 0; q < 4; q++) {
        offx[q] = __ldg(offset_table + obase[q] + 0);
        offy[q] = __ldg(offset_table + obase[q] + 1);
        offz[q] = __ldg(offset_table + obase[q] + 2);
    }

    // Stage 3: hash indices (floored mod 256 == &255); max index 2^25 fits in int32
    int hbase[4];
    #pragma unroll
    for (int q = 0; q < 4; q++) {
        int hx = (((int)((float)cs[3*q + 0] * m0x)) + offx[q]) & 255;
        int hy = (((int)((float)cs[3*q + 1] * m0y)) + offy[q]) & 255;
        int hz = (((int)((float)cs[3*q + 2] * m0z)) + offz[q]) & 255;
        // float4 index: each entry is 8 floats = 2 float4
        hbase[q] = ((hx * 256 + hy) * 256 + hz) * 2;
    }

    // Stage 4: gather 32B features per query (random DRAM, DEFAULT cache policy
    // so L2 can serve the ~38% of queries that re-touch an already-fetched line)
    float4 f0[4], f1[4];
    #pragma unroll
    for (int q = 0; q < 4; q++) {
        f0[q] = hash_table[hbase[q] + 0];
        f1[q] = hash_table[hbase[q] + 1];
    }

    // Stage 5: streaming stores (no reuse -> evict-first, keep L2 for the tables)
    #pragma unroll
    for (int q = 0; q < 4; q++) {
        if (q0 + q < nq) {
            __stcs(out + (q0 + q) * 2 + 0, f0[q]);
            __stcs(out + (q0 + q) * 2 + 1, f1[q]);
        }
    }
}

extern "C" void kernel_launch(void* const* d_in, const int* in_sizes, int n_in,
                              void* d_out, int out_size)
{
    const int*    coords     = (const int*)   d_in[0];
    const float4* hash_table = (const float4*)d_in[1];
    const int*    offset_tab = (const int*)   d_in[2];
    const float*  m0         = (const float*) d_in[3];
    const float*  m1         = (const float*) d_in[4];
    float4*       out        = (float4*)      d_out;

    const int nq = in_sizes[0] / 3;
    const int nthreads = (nq + 3) / 4;
    const int block = 256;
    const int grid = (nthreads + block - 1) / block;
    psh_kernel<<<grid, block>>>(coords, hash_table, offset_tab, m0, m1, out, nq);
}